// round 3
// baseline (speedup 1.0000x reference)
#include <cuda_runtime.h>
#include <cuda_bf16.h>
#include <stdint.h>

#define NN 16384
#define KDIM 128
#define CAP 96

typedef unsigned long long u64;

// ---------------- scratch (device globals; no dynamic alloc allowed) --------
__device__ int   g_deg[NN];
__device__ int   g_ell[NN * CAP];    // ELL source lists (by target), slot order arbitrary
__device__ float g_agg[NN * KDIM];
__device__ float g_h0[NN * KDIM];
__device__ float g_h1[NN * KDIM];

// ---------------- f32x2 packed helpers --------------------------------------
__device__ __forceinline__ void fma2(u64& d, u64 a, u64 b) {
    asm("fma.rn.f32x2 %0, %1, %2, %0;" : "+l"(d) : "l"(a), "l"(b));
}
__device__ __forceinline__ u64 dup2(float w) {
    u64 r;
    asm("mov.b64 %0, {%1, %1};" : "=l"(r) : "f"(w));
    return r;
}
__device__ __forceinline__ void unpack2(u64 v, float& lo, float& hi) {
    asm("mov.b64 {%0, %1}, %2;" : "=f"(lo), "=f"(hi) : "l"(v));
}

// ---------------- init -------------------------------------------------------
__global__ void init_kernel() {
    int i = blockIdx.x * blockDim.x + threadIdx.x;
    if (i < NN) g_deg[i] = 0;
}

// ---------------- pass A: stream adj once, scatter edges straight to ELL -----
__global__ void scan_adj_kernel(const float4* __restrict__ adj4) {
    const int total4 = (NN / 4) * NN;  // 67,108,864 float4
    const int stride = gridDim.x * blockDim.x;
    const int tid = blockIdx.x * blockDim.x + threadIdx.x;
    const int iters = (total4 + 4 * stride - 1) / (4 * stride);

    for (int it = 0; it < iters; it++) {
        int base = tid + it * 4 * stride;
        float4 v[4];
        int idx[4];
#pragma unroll
        for (int j = 0; j < 4; j++) {
            idx[j] = base + j * stride;
            if (idx[j] < total4) v[j] = __ldcs(&adj4[idx[j]]);
            else                 v[j] = make_float4(0.f, 0.f, 0.f, 0.f);
        }
#pragma unroll
        for (int j = 0; j < 4; j++) {
            int m = ((v[j].x != 0.f) ? 1 : 0) | ((v[j].y != 0.f) ? 2 : 0) |
                    ((v[j].z != 0.f) ? 4 : 0) | ((v[j].w != 0.f) ? 8 : 0);
            if (__any_sync(0xffffffffu, m != 0)) {
                int e4 = idx[j] * 4;
#pragma unroll
                for (int b = 0; b < 4; b++) {
                    if (m & (1 << b)) {
                        int elem = e4 + b;
                        int c = elem & (NN - 1);      // target node
                        int r = elem >> 14;           // source node
                        int slot = atomicAdd(&g_deg[c], 1);
                        if (slot < CAP) g_ell[c * CAP + slot] = r;
                    }
                }
            }
        }
    }
}

// ---------------- mean aggregation: one warp per target node (ELL) ----------
__global__ void aggregate_kernel(const float* __restrict__ xin) {
    int w = (blockIdx.x * blockDim.x + threadIdx.x) >> 5;
    int lane = threadIdx.x & 31;
    if (w >= NN) return;
    int deg = g_deg[w];
    if (deg > CAP) deg = CAP;
    const int* __restrict__ src = &g_ell[w * CAP];
    const float4* __restrict__ x4 = (const float4*)xin;
    float4 acc = make_float4(0.f, 0.f, 0.f, 0.f);
    int e = 0;
    for (; e + 4 <= deg; e += 4) {
        int s0 = __ldg(&src[e + 0]);
        int s1 = __ldg(&src[e + 1]);
        int s2 = __ldg(&src[e + 2]);
        int s3 = __ldg(&src[e + 3]);
        float4 v0 = __ldg(&x4[s0 * 32 + lane]);
        float4 v1 = __ldg(&x4[s1 * 32 + lane]);
        float4 v2 = __ldg(&x4[s2 * 32 + lane]);
        float4 v3 = __ldg(&x4[s3 * 32 + lane]);
        acc.x += v0.x + v1.x + v2.x + v3.x;
        acc.y += v0.y + v1.y + v2.y + v3.y;
        acc.z += v0.z + v1.z + v2.z + v3.z;
        acc.w += v0.w + v1.w + v2.w + v3.w;
    }
    for (; e < deg; e++) {
        int s = __ldg(&src[e]);
        float4 v = __ldg(&x4[s * 32 + lane]);
        acc.x += v.x; acc.y += v.y; acc.z += v.z; acc.w += v.w;
    }
    float di = (deg > 0) ? (1.0f / (float)deg) : 0.0f;
    float4 r = make_float4(acc.x * di, acc.y * di, acc.z * di, acc.w * di);
    ((float4*)g_agg)[w * 32 + lane] = r;
}

// ---------------- fused dual GEMM: out = agg@Wl.T + b + xin@Wr.T ------------
// f-paired f32x2 layout: W pairs load as LDS.64, A scalars dup'd.
// Tile: 64 nodes x FO outputs, 256 threads; thread = 2 nodes x FJ f-pairs.
template <int FO, bool RELU>
__global__ __launch_bounds__(256) void gemm_kernel(
    const float* __restrict__ A1, const float* __restrict__ A2,
    const float* __restrict__ Wl, const float* __restrict__ b,
    const float* __restrict__ Wr, float* __restrict__ out) {
    constexpr int KC = 16;
    constexpr int NT = 64;               // nodes per block
    constexpr int FJ = FO / 16;          // f-pairs per thread
    __shared__ float sA1[KC][NT + 4];
    __shared__ float sA2[KC][NT + 4];
    __shared__ float sWl[KC][FO + 4];
    __shared__ float sWr[KC][FO + 4];

    const int tid = threadIdx.x;
    const int tx = tid & 7;              // f-pair lane: fp = tx + 8*j
    const int ty = tid >> 3;             // node group: n0 = ty*2  (ty in [0,32))
    const int n0 = ty * 2;
    const int nb = blockIdx.x * NT;

    u64 acc[2][FJ];
#pragma unroll
    for (int p = 0; p < 2; p++)
#pragma unroll
        for (int j = 0; j < FJ; j++) acc[p][j] = 0ull;

    const int kq = (tid & 3) * 4;        // k offset within chunk
    const int rr = tid >> 2;             // 0..63

    for (int kc0 = 0; kc0 < KDIM; kc0 += KC) {
        {   // A tiles: 64 nodes, each thread one float4 per matrix
            int n = rr;
            float4 va = *(const float4*)&A1[(nb + n) * KDIM + kc0 + kq];
            sA1[kq + 0][n] = va.x; sA1[kq + 1][n] = va.y;
            sA1[kq + 2][n] = va.z; sA1[kq + 3][n] = va.w;
            float4 vb = *(const float4*)&A2[(nb + n) * KDIM + kc0 + kq];
            sA2[kq + 0][n] = vb.x; sA2[kq + 1][n] = vb.y;
            sA2[kq + 2][n] = vb.z; sA2[kq + 3][n] = vb.w;
        }
        for (int f = rr; f < FO; f += 64) {
            float4 wv = *(const float4*)&Wl[f * KDIM + kc0 + kq];
            sWl[kq + 0][f] = wv.x; sWl[kq + 1][f] = wv.y;
            sWl[kq + 2][f] = wv.z; sWl[kq + 3][f] = wv.w;
            float4 wu = *(const float4*)&Wr[f * KDIM + kc0 + kq];
            sWr[kq + 0][f] = wu.x; sWr[kq + 1][f] = wu.y;
            sWr[kq + 2][f] = wu.z; sWr[kq + 3][f] = wu.w;
        }
        __syncthreads();

#pragma unroll 4
        for (int kk = 0; kk < KC; kk++) {
            u64 A10 = dup2(sA1[kk][n0 + 0]);
            u64 A11 = dup2(sA1[kk][n0 + 1]);
            u64 A20 = dup2(sA2[kk][n0 + 0]);
            u64 A21 = dup2(sA2[kk][n0 + 1]);
#pragma unroll
            for (int j = 0; j < FJ; j++) {
                int f2 = 2 * (tx + 8 * j);
                u64 wl = *reinterpret_cast<const u64*>(&sWl[kk][f2]);
                u64 wr = *reinterpret_cast<const u64*>(&sWr[kk][f2]);
                fma2(acc[0][j], wl, A10);
                fma2(acc[0][j], wr, A20);
                fma2(acc[1][j], wl, A11);
                fma2(acc[1][j], wr, A21);
            }
        }
        __syncthreads();
    }

#pragma unroll
    for (int j = 0; j < FJ; j++) {
        int f2 = 2 * (tx + 8 * j);
        float2 bv = *(const float2*)&b[f2];
#pragma unroll
        for (int p = 0; p < 2; p++) {
            float lo, hi;
            unpack2(acc[p][j], lo, hi);
            lo += bv.x; hi += bv.y;
            if (RELU) { lo = fmaxf(lo, 0.f); hi = fmaxf(hi, 0.f); }
            int n = nb + n0 + p;
            *(float2*)&out[n * FO + f2] = make_float2(lo, hi);
        }
    }
}

// ---------------- launch -----------------------------------------------------
extern "C" void kernel_launch(void* const* d_in, const int* in_sizes, int n_in,
                              void* d_out, int out_size) {
    const float* x   = (const float*)d_in[0];
    const float* adj = (const float*)d_in[1];
    const float* Wl0 = (const float*)d_in[2];
    const float* b0  = (const float*)d_in[3];
    const float* Wr0 = (const float*)d_in[4];
    const float* Wl1 = (const float*)d_in[5];
    const float* b1  = (const float*)d_in[6];
    const float* Wr1 = (const float*)d_in[7];
    const float* Wl2 = (const float*)d_in[8];
    const float* b2  = (const float*)d_in[9];
    const float* Wr2 = (const float*)d_in[10];
    float* out = (float*)d_out;

    float *p_agg, *p_h0, *p_h1;
    cudaGetSymbolAddress((void**)&p_agg, g_agg);
    cudaGetSymbolAddress((void**)&p_h0, g_h0);
    cudaGetSymbolAddress((void**)&p_h1, g_h1);

    init_kernel<<<64, 256>>>();
    scan_adj_kernel<<<1184, 256>>>((const float4*)adj);

    // layer 0
    aggregate_kernel<<<2048, 256>>>(x);
    gemm_kernel<128, true><<<256, 256>>>(p_agg, x, Wl0, b0, Wr0, p_h0);
    // layer 1
    aggregate_kernel<<<2048, 256>>>(p_h0);
    gemm_kernel<128, true><<<256, 256>>>(p_agg, p_h0, Wl1, b1, Wr1, p_h1);
    // layer 2
    aggregate_kernel<<<2048, 256>>>(p_h1);
    gemm_kernel<64, false><<<256, 256>>>(p_agg, p_h1, Wl2, b2, Wr2, out);
}

// round 4
// speedup vs baseline: 1.1042x; 1.1042x over previous
#include <cuda_runtime.h>
#include <cuda_bf16.h>
#include <stdint.h>

#define NN 16384
#define KDIM 128
#define CAP 96

typedef unsigned long long u64;

// ---------------- scratch (device globals; no dynamic alloc allowed) --------
__device__ int   g_deg[NN];
__device__ int   g_ell[NN * CAP];    // ELL source lists (by target), slot order arbitrary
__device__ float g_agg[NN * KDIM];
__device__ float g_h0[NN * KDIM];
__device__ float g_h1[NN * KDIM];

// ---------------- f32x2 packed helpers --------------------------------------
__device__ __forceinline__ void fma2(u64& d, u64 a, u64 b) {
    asm("fma.rn.f32x2 %0, %1, %2, %0;" : "+l"(d) : "l"(a), "l"(b));
}
__device__ __forceinline__ u64 dup2(float w) {
    u64 r;
    asm("mov.b64 %0, {%1, %1};" : "=l"(r) : "f"(w));
    return r;
}
__device__ __forceinline__ void unpack2(u64 v, float& lo, float& hi) {
    asm("mov.b64 {%0, %1}, %2;" : "=f"(lo), "=f"(hi) : "l"(v));
}

// ---------------- init -------------------------------------------------------
__global__ void init_kernel() {
    int i = blockIdx.x * blockDim.x + threadIdx.x;
    if (i < NN) g_deg[i] = 0;
}

// ---------------- pass A: stream adj once, scatter edges straight to ELL -----
__global__ void scan_adj_kernel(const float4* __restrict__ adj4) {
    const int total4 = (NN / 4) * NN;  // 67,108,864 float4
    const int stride = gridDim.x * blockDim.x;
    const int tid = blockIdx.x * blockDim.x + threadIdx.x;
    const int iters = (total4 + 4 * stride - 1) / (4 * stride);

    for (int it = 0; it < iters; it++) {
        int base = tid + it * 4 * stride;
        float4 v[4];
        int idx[4];
#pragma unroll
        for (int j = 0; j < 4; j++) {
            idx[j] = base + j * stride;
            if (idx[j] < total4) v[j] = __ldcs(&adj4[idx[j]]);
            else                 v[j] = make_float4(0.f, 0.f, 0.f, 0.f);
        }
#pragma unroll
        for (int j = 0; j < 4; j++) {
            int m = ((v[j].x != 0.f) ? 1 : 0) | ((v[j].y != 0.f) ? 2 : 0) |
                    ((v[j].z != 0.f) ? 4 : 0) | ((v[j].w != 0.f) ? 8 : 0);
            if (__any_sync(0xffffffffu, m != 0)) {
                int e4 = idx[j] * 4;
#pragma unroll
                for (int b = 0; b < 4; b++) {
                    if (m & (1 << b)) {
                        int elem = e4 + b;
                        int c = elem & (NN - 1);      // target node
                        int r = elem >> 14;           // source node
                        int slot = atomicAdd(&g_deg[c], 1);
                        if (slot < CAP) g_ell[c * CAP + slot] = r;
                    }
                }
            }
        }
    }
}

// ---------------- mean aggregation: one warp per target node (ELL) ----------
__global__ void aggregate_kernel(const float* __restrict__ xin) {
    int w = (blockIdx.x * blockDim.x + threadIdx.x) >> 5;
    int lane = threadIdx.x & 31;
    if (w >= NN) return;
    int deg = g_deg[w];
    if (deg > CAP) deg = CAP;
    const int* __restrict__ src = &g_ell[w * CAP];
    const float4* __restrict__ x4 = (const float4*)xin;
    float4 acc = make_float4(0.f, 0.f, 0.f, 0.f);
    int e = 0;
    for (; e + 4 <= deg; e += 4) {
        int s0 = __ldg(&src[e + 0]);
        int s1 = __ldg(&src[e + 1]);
        int s2 = __ldg(&src[e + 2]);
        int s3 = __ldg(&src[e + 3]);
        float4 v0 = __ldg(&x4[s0 * 32 + lane]);
        float4 v1 = __ldg(&x4[s1 * 32 + lane]);
        float4 v2 = __ldg(&x4[s2 * 32 + lane]);
        float4 v3 = __ldg(&x4[s3 * 32 + lane]);
        acc.x += v0.x + v1.x + v2.x + v3.x;
        acc.y += v0.y + v1.y + v2.y + v3.y;
        acc.z += v0.z + v1.z + v2.z + v3.z;
        acc.w += v0.w + v1.w + v2.w + v3.w;
    }
    for (; e < deg; e++) {
        int s = __ldg(&src[e]);
        float4 v = __ldg(&x4[s * 32 + lane]);
        acc.x += v.x; acc.y += v.y; acc.z += v.z; acc.w += v.w;
    }
    float di = (deg > 0) ? (1.0f / (float)deg) : 0.0f;
    float4 r = make_float4(acc.x * di, acc.y * di, acc.z * di, acc.w * di);
    ((float4*)g_agg)[w * 32 + lane] = r;
}

// ---------------- fused dual GEMM: out = agg@Wl.T + b + xin@Wr.T ------------
// R2 inner loop (node-paired f32x2, broadcast W), FO split across blockIdx.y
// to cut acc registers in half -> 3 CTAs/SM.
// Block tile: 128 nodes x 64 outputs, 256 threads, KC=16 chunks.
template <int FO, bool RELU>
__global__ __launch_bounds__(256, 3) void gemm_kernel(
    const float* __restrict__ A1, const float* __restrict__ A2,
    const float* __restrict__ Wl, const float* __restrict__ b,
    const float* __restrict__ Wr, float* __restrict__ out) {
    constexpr int KC = 16;
    constexpr int FOB = 64;              // outputs per block
    constexpr int FJ = FOB / 16;         // 4
    __shared__ float sA1[KC][132];
    __shared__ float sA2[KC][132];
    __shared__ float sWl[KC][FOB + 4];
    __shared__ float sWr[KC][FOB + 4];

    const int tid = threadIdx.x;
    const int tx = tid & 15;             // output lane: f = tx + 16*j
    const int ty = tid >> 4;             // node group: n0 = ty*8
    const int n0 = ty * 8;
    const int nb = blockIdx.x * 128;
    const int fb = blockIdx.y * FOB;     // output-feature block offset

    u64 acc[4][FJ];
#pragma unroll
    for (int p = 0; p < 4; p++)
#pragma unroll
        for (int j = 0; j < FJ; j++) acc[p][j] = 0ull;

    const int kq = (tid & 3) * 4;        // k offset within chunk
    const int rr = tid >> 2;             // 0..63

    for (int kc0 = 0; kc0 < KDIM; kc0 += KC) {
#pragma unroll
        for (int h = 0; h < 2; h++) {
            int n = rr + h * 64;
            float4 va = *(const float4*)&A1[(nb + n) * KDIM + kc0 + kq];
            sA1[kq + 0][n] = va.x; sA1[kq + 1][n] = va.y;
            sA1[kq + 2][n] = va.z; sA1[kq + 3][n] = va.w;
            float4 vb = *(const float4*)&A2[(nb + n) * KDIM + kc0 + kq];
            sA2[kq + 0][n] = vb.x; sA2[kq + 1][n] = vb.y;
            sA2[kq + 2][n] = vb.z; sA2[kq + 3][n] = vb.w;
        }
        {   // W tiles: 64 rows of this f-block
            int f = rr;
            float4 wv = *(const float4*)&Wl[(fb + f) * KDIM + kc0 + kq];
            sWl[kq + 0][f] = wv.x; sWl[kq + 1][f] = wv.y;
            sWl[kq + 2][f] = wv.z; sWl[kq + 3][f] = wv.w;
            float4 wu = *(const float4*)&Wr[(fb + f) * KDIM + kc0 + kq];
            sWr[kq + 0][f] = wu.x; sWr[kq + 1][f] = wu.y;
            sWr[kq + 2][f] = wu.z; sWr[kq + 3][f] = wu.w;
        }
        __syncthreads();

#pragma unroll 4
        for (int kk = 0; kk < KC; kk++) {
            const u64* pa1 = reinterpret_cast<const u64*>(&sA1[kk][n0]);
            const u64* pa2 = reinterpret_cast<const u64*>(&sA2[kk][n0]);
            u64 a1[4], a2[4];
#pragma unroll
            for (int p = 0; p < 4; p++) { a1[p] = pa1[p]; a2[p] = pa2[p]; }
#pragma unroll
            for (int j = 0; j < FJ; j++) {
                u64 wl2 = dup2(sWl[kk][tx + 16 * j]);
                u64 wr2 = dup2(sWr[kk][tx + 16 * j]);
#pragma unroll
                for (int p = 0; p < 4; p++) {
                    fma2(acc[p][j], a1[p], wl2);
                    fma2(acc[p][j], a2[p], wr2);
                }
            }
        }
        __syncthreads();
    }

#pragma unroll
    for (int j = 0; j < FJ; j++) {
        int f = fb + tx + 16 * j;
        float bv = __ldg(&b[f]);
#pragma unroll
        for (int p = 0; p < 4; p++) {
            float lo, hi;
            unpack2(acc[p][j], lo, hi);
            lo += bv; hi += bv;
            if (RELU) { lo = fmaxf(lo, 0.f); hi = fmaxf(hi, 0.f); }
            int n = nb + n0 + 2 * p;
            out[n * FO + f] = lo;
            out[(n + 1) * FO + f] = hi;
        }
    }
}

// ---------------- launch -----------------------------------------------------
extern "C" void kernel_launch(void* const* d_in, const int* in_sizes, int n_in,
                              void* d_out, int out_size) {
    const float* x   = (const float*)d_in[0];
    const float* adj = (const float*)d_in[1];
    const float* Wl0 = (const float*)d_in[2];
    const float* b0  = (const float*)d_in[3];
    const float* Wr0 = (const float*)d_in[4];
    const float* Wl1 = (const float*)d_in[5];
    const float* b1  = (const float*)d_in[6];
    const float* Wr1 = (const float*)d_in[7];
    const float* Wl2 = (const float*)d_in[8];
    const float* b2  = (const float*)d_in[9];
    const float* Wr2 = (const float*)d_in[10];
    float* out = (float*)d_out;

    float *p_agg, *p_h0, *p_h1;
    cudaGetSymbolAddress((void**)&p_agg, g_agg);
    cudaGetSymbolAddress((void**)&p_h0, g_h0);
    cudaGetSymbolAddress((void**)&p_h1, g_h1);

    init_kernel<<<64, 256>>>();
    scan_adj_kernel<<<1184, 256>>>((const float4*)adj);

    dim3 g128(128, 2);   // 128 node-blocks x 2 f-blocks (FO=128)
    dim3 g64(128, 1);    // FO=64: single f-block

    // layer 0
    aggregate_kernel<<<2048, 256>>>(x);
    gemm_kernel<128, true><<<g128, 256>>>(p_agg, x, Wl0, b0, Wr0, p_h0);
    // layer 1
    aggregate_kernel<<<2048, 256>>>(p_h0);
    gemm_kernel<128, true><<<g128, 256>>>(p_agg, p_h0, Wl1, b1, Wr1, p_h1);
    // layer 2
    aggregate_kernel<<<2048, 256>>>(p_h1);
    gemm_kernel<64, false><<<g64, 256>>>(p_agg, p_h1, Wl2, b2, Wr2, out);
}

// round 5
// speedup vs baseline: 1.1455x; 1.0374x over previous
#include <cuda_runtime.h>
#include <cuda_bf16.h>
#include <stdint.h>

#define NN 16384
#define KDIM 128
#define CAP 96

typedef unsigned long long u64;

// ---------------- scratch (device globals; no dynamic alloc allowed) --------
__device__ int   g_deg[NN];
__device__ int   g_ell[NN * CAP];    // ELL source lists (by target), slot order arbitrary
__device__ float g_agg[NN * KDIM];
__device__ float g_h0[NN * KDIM];
__device__ float g_h1[NN * KDIM];
__device__ float g_xr[NN * KDIM];    // x @ Wr.T partial (reused per layer)

// ---------------- f32x2 packed helpers --------------------------------------
__device__ __forceinline__ void fma2(u64& d, u64 a, u64 b) {
    asm("fma.rn.f32x2 %0, %1, %2, %0;" : "+l"(d) : "l"(a), "l"(b));
}
__device__ __forceinline__ u64 dup2(float w) {
    u64 r;
    asm("mov.b64 %0, {%1, %1};" : "=l"(r) : "f"(w));
    return r;
}
__device__ __forceinline__ void unpack2(u64 v, float& lo, float& hi) {
    asm("mov.b64 {%0, %1}, %2;" : "=f"(lo), "=f"(hi) : "l"(v));
}

// ---------------- init -------------------------------------------------------
__global__ void init_kernel() {
    int i = blockIdx.x * blockDim.x + threadIdx.x;
    if (i < NN) g_deg[i] = 0;
}

// ---------------- pass A: stream adj once, scatter edges straight to ELL -----
// 1024 blocks x 256 threads = 262144 threads; 256 float4/thread, exact division.
__global__ void scan_adj_kernel(const float4* __restrict__ adj4) {
    const int stride = gridDim.x * blockDim.x;   // 262144
    const int tid = blockIdx.x * blockDim.x + threadIdx.x;
#pragma unroll 1
    for (int it = 0; it < 32; it++) {
        int base = tid + it * 8 * stride;
        float4 v[8];
#pragma unroll
        for (int j = 0; j < 8; j++) v[j] = __ldcs(&adj4[base + j * stride]);
#pragma unroll
        for (int j = 0; j < 8; j++) {
            int m = ((__float_as_int(v[j].x) != 0) ? 1 : 0) |
                    ((__float_as_int(v[j].y) != 0) ? 2 : 0) |
                    ((__float_as_int(v[j].z) != 0) ? 4 : 0) |
                    ((__float_as_int(v[j].w) != 0) ? 8 : 0);
            if (__any_sync(0xffffffffu, m != 0)) {
                int e4 = (base + j * stride) * 4;
#pragma unroll
                for (int b = 0; b < 4; b++) {
                    if (m & (1 << b)) {
                        int elem = e4 + b;
                        int c = elem & (NN - 1);      // target node
                        int r = elem >> 14;           // source node
                        int slot = atomicAdd(&g_deg[c], 1);
                        if (slot < CAP) g_ell[c * CAP + slot] = r;
                    }
                }
            }
        }
    }
}

// ---------------- mean aggregation: one warp per target node (ELL) ----------
__global__ void aggregate_kernel(const float* __restrict__ xin) {
    int w = (blockIdx.x * blockDim.x + threadIdx.x) >> 5;
    int lane = threadIdx.x & 31;
    if (w >= NN) return;
    int deg = g_deg[w];
    if (deg > CAP) deg = CAP;
    const int* __restrict__ src = &g_ell[w * CAP];
    const float4* __restrict__ x4 = (const float4*)xin;
    float4 acc = make_float4(0.f, 0.f, 0.f, 0.f);
    int e = 0;
    for (; e + 4 <= deg; e += 4) {
        int s0 = __ldg(&src[e + 0]);
        int s1 = __ldg(&src[e + 1]);
        int s2 = __ldg(&src[e + 2]);
        int s3 = __ldg(&src[e + 3]);
        float4 v0 = __ldg(&x4[s0 * 32 + lane]);
        float4 v1 = __ldg(&x4[s1 * 32 + lane]);
        float4 v2 = __ldg(&x4[s2 * 32 + lane]);
        float4 v3 = __ldg(&x4[s3 * 32 + lane]);
        acc.x += v0.x + v1.x + v2.x + v3.x;
        acc.y += v0.y + v1.y + v2.y + v3.y;
        acc.z += v0.z + v1.z + v2.z + v3.z;
        acc.w += v0.w + v1.w + v2.w + v3.w;
    }
    for (; e < deg; e++) {
        int s = __ldg(&src[e]);
        float4 v = __ldg(&x4[s * 32 + lane]);
        acc.x += v.x; acc.y += v.y; acc.z += v.z; acc.w += v.w;
    }
    float di = (deg > 0) ? (1.0f / (float)deg) : 0.0f;
    float4 r = make_float4(acc.x * di, acc.y * di, acc.z * di, acc.w * di);
    ((float4*)g_agg)[w * 32 + lane] = r;
}

// ---------------- single GEMM: out = A @ W.T  (+ b + XR, optional relu) -----
// Node-paired f32x2 (broadcast W), 128 nodes x 64 outputs per block.
// EPI 0: plain store (XR pass).  EPI 1: + b + XR, relu.  EPI 2: + b + XR.
template <int FO, int EPI>
__global__ __launch_bounds__(256, 4) void sgemm_kernel(
    const float* __restrict__ A, const float* __restrict__ W,
    const float* __restrict__ b, const float* __restrict__ XR,
    float* __restrict__ out) {
    constexpr int KC = 16;
    constexpr int FOB = 64;
    constexpr int FJ = FOB / 16;         // 4
    __shared__ float sA[KC][132];
    __shared__ float sW[KC][FOB + 4];

    const int tid = threadIdx.x;
    const int tx = tid & 15;             // f = fb + tx + 16*j
    const int ty = tid >> 4;             // n0 = ty*8
    const int n0 = ty * 8;
    const int nb = blockIdx.x * 128;
    const int fb = blockIdx.y * FOB;

    u64 acc[4][FJ];
#pragma unroll
    for (int p = 0; p < 4; p++)
#pragma unroll
        for (int j = 0; j < FJ; j++) acc[p][j] = 0ull;

    const int kq = (tid & 3) * 4;
    const int rr = tid >> 2;             // 0..63

    for (int kc0 = 0; kc0 < KDIM; kc0 += KC) {
#pragma unroll
        for (int h = 0; h < 2; h++) {
            int n = rr + h * 64;
            float4 va = *(const float4*)&A[(nb + n) * KDIM + kc0 + kq];
            sA[kq + 0][n] = va.x; sA[kq + 1][n] = va.y;
            sA[kq + 2][n] = va.z; sA[kq + 3][n] = va.w;
        }
        {
            int f = rr;
            float4 wv = *(const float4*)&W[(fb + f) * KDIM + kc0 + kq];
            sW[kq + 0][f] = wv.x; sW[kq + 1][f] = wv.y;
            sW[kq + 2][f] = wv.z; sW[kq + 3][f] = wv.w;
        }
        __syncthreads();

#pragma unroll 4
        for (int kk = 0; kk < KC; kk++) {
            const u64* pa = reinterpret_cast<const u64*>(&sA[kk][n0]);
            u64 a[4];
#pragma unroll
            for (int p = 0; p < 4; p++) a[p] = pa[p];
#pragma unroll
            for (int j = 0; j < FJ; j++) {
                u64 w2 = dup2(sW[kk][tx + 16 * j]);
#pragma unroll
                for (int p = 0; p < 4; p++) fma2(acc[p][j], a[p], w2);
            }
        }
        __syncthreads();
    }

#pragma unroll
    for (int j = 0; j < FJ; j++) {
        int f = fb + tx + 16 * j;
        float bv = (EPI != 0) ? __ldg(&b[f]) : 0.0f;
#pragma unroll
        for (int p = 0; p < 4; p++) {
            float lo, hi;
            unpack2(acc[p][j], lo, hi);
            int n = nb + n0 + 2 * p;
            if (EPI != 0) {
                lo += bv + __ldg(&XR[n * FO + f]);
                hi += bv + __ldg(&XR[(n + 1) * FO + f]);
                if (EPI == 1) { lo = fmaxf(lo, 0.f); hi = fmaxf(hi, 0.f); }
            }
            out[n * FO + f] = lo;
            out[(n + 1) * FO + f] = hi;
        }
    }
}

// ---------------- launch -----------------------------------------------------
extern "C" void kernel_launch(void* const* d_in, const int* in_sizes, int n_in,
                              void* d_out, int out_size) {
    const float* x   = (const float*)d_in[0];
    const float* adj = (const float*)d_in[1];
    const float* Wl0 = (const float*)d_in[2];
    const float* b0  = (const float*)d_in[3];
    const float* Wr0 = (const float*)d_in[4];
    const float* Wl1 = (const float*)d_in[5];
    const float* b1  = (const float*)d_in[6];
    const float* Wr1 = (const float*)d_in[7];
    const float* Wl2 = (const float*)d_in[8];
    const float* b2  = (const float*)d_in[9];
    const float* Wr2 = (const float*)d_in[10];
    float* out = (float*)d_out;

    float *p_agg, *p_h0, *p_h1, *p_xr;
    cudaGetSymbolAddress((void**)&p_agg, g_agg);
    cudaGetSymbolAddress((void**)&p_h0, g_h0);
    cudaGetSymbolAddress((void**)&p_h1, g_h1);
    cudaGetSymbolAddress((void**)&p_xr, g_xr);

    // side stream + events (created once on first, non-captured call; the
    // sequence of launched work is identical on every call)
    static cudaStream_t s2 = nullptr;
    static cudaEvent_t evF0, evX0, evF1, evX1, evF2, evX2;
    if (s2 == nullptr) {
        cudaStreamCreateWithFlags(&s2, cudaStreamNonBlocking);
        cudaEventCreateWithFlags(&evF0, cudaEventDisableTiming);
        cudaEventCreateWithFlags(&evX0, cudaEventDisableTiming);
        cudaEventCreateWithFlags(&evF1, cudaEventDisableTiming);
        cudaEventCreateWithFlags(&evX1, cudaEventDisableTiming);
        cudaEventCreateWithFlags(&evF2, cudaEventDisableTiming);
        cudaEventCreateWithFlags(&evX2, cudaEventDisableTiming);
    }

    dim3 g128(128, 2);   // FO=128
    dim3 g64(128, 1);    // FO=64

    init_kernel<<<64, 256>>>();

    // fork: XR0 = x @ Wr0.T on s2, overlapping the adj scan
    cudaEventRecord(evF0, 0);
    cudaStreamWaitEvent(s2, evF0, 0);
    sgemm_kernel<128, 0><<<g128, 256, 0, s2>>>(x, Wr0, nullptr, nullptr, p_xr);
    cudaEventRecord(evX0, s2);

    scan_adj_kernel<<<1024, 256>>>((const float4*)adj);

    // layer 0
    aggregate_kernel<<<2048, 256>>>(x);
    cudaStreamWaitEvent(0, evX0, 0);
    sgemm_kernel<128, 1><<<g128, 256>>>(p_agg, Wl0, b0, p_xr, p_h0);

    // layer 1: XR1 = h0 @ Wr1.T on s2, overlapping aggregate(h0)
    cudaEventRecord(evF1, 0);
    cudaStreamWaitEvent(s2, evF1, 0);
    sgemm_kernel<128, 0><<<g128, 256, 0, s2>>>(p_h0, Wr1, nullptr, nullptr, p_xr);
    cudaEventRecord(evX1, s2);
    aggregate_kernel<<<2048, 256>>>(p_h0);
    cudaStreamWaitEvent(0, evX1, 0);
    sgemm_kernel<128, 1><<<g128, 256>>>(p_agg, Wl1, b1, p_xr, p_h1);

    // layer 2: XR2 = h1 @ Wr2.T on s2, overlapping aggregate(h1)
    cudaEventRecord(evF2, 0);
    cudaStreamWaitEvent(s2, evF2, 0);
    sgemm_kernel<64, 0><<<g64, 256, 0, s2>>>(p_h1, Wr2, nullptr, nullptr, p_xr);
    cudaEventRecord(evX2, s2);
    aggregate_kernel<<<2048, 256>>>(p_h1);
    cudaStreamWaitEvent(0, evX2, 0);
    sgemm_kernel<64, 2><<<g64, 256>>>(p_agg, Wl2, b2, p_xr, out);
}